// round 10
// baseline (speedup 1.0000x reference)
#include <cuda_runtime.h>
#include <math.h>

// loss = sum_c logdet(G_c + 0.5 I_128) - logdet(G + 0.5 I_128) + 1920*ln2
// where G_c = F_c^T F_c (per-class 128x128 Gram), G = sum_c G_c.
// Derivation: det(sI_m + F F^T) = s^(m-k) det(sI_k + F^T F).
//
// Single fused persistent kernel, 128 blocks (all co-resident: 128 < 148 SMs):
//   phase A: block b = (class c = b>>3, slab s = b&7) computes the 128x16
//            column slab G_c[:, 16s:16s+16] directly (no accumulation).
//   device-wide release/acquire barrier on counter A.
//   phase B: blocks 0..16 run register-resident symmetric elimination
//            (block 16 sums the 16 class Grams at load). Signed logdets are
//            atomicAdd'ed into g_acc; last block (counter B) writes out[0]
//            and resets all device state to zero for graph replay.

#define MF 1536
#define KD 128
#define NC 16
#define NSLAB 8
#define SLABW 16                  // KD / NSLAB
#define GRID_N (NC * NSLAB)       // 128 blocks
#define NCHOL (NC + 1)            // 17 logdets

__device__ __align__(16) float g_gram[NC][KD][KD];
__device__ float    g_acc;        // zero-init; reset to 0 each run
__device__ unsigned g_ctrA;       // zero-init; reset to 0 each run
__device__ unsigned g_ctrB;       // zero-init; reset to 0 each run

__global__ __launch_bounds__(512) void fused_kernel(const float* __restrict__ feats,
                                                    const int* __restrict__ labels,
                                                    float* __restrict__ out) {
    const int b   = blockIdx.x;
    const int tid = threadIdx.x;
    const int i   = tid & 127;    // row index (both phases)
    const int h   = tid >> 7;     // 0..3   (both phases)

    __shared__ int   s_idx[MF];
    __shared__ int   s_cnt;
    __shared__ __align__(16) float s_rows[16][KD];
    __shared__ __align__(16) float s_rowk[2][KD];
    __shared__ float s_piv[KD];
    __shared__ float s_red[4];

    // ---------------- Phase A: Gram slab (all 128 blocks) ----------------
    {
        const int c  = b >> 3;           // class
        const int sl = b & 7;            // slab
        const int cb = SLABW * sl + 4 * h;   // this thread's 4 output cols

        if (tid == 0) s_cnt = 0;
        __syncthreads();
        for (int m = tid; m < MF; m += 512)
            if (labels[m] == c) s_idx[atomicAdd(&s_cnt, 1)] = m;
        __syncthreads();
        const int cnt = s_cnt;

        float a0 = 0.f, a1 = 0.f, a2 = 0.f, a3 = 0.f;
        for (int rb = 0; rb < cnt; rb += 16) {
            __syncthreads();
            {   // 16 rows x 128 floats = 512 float4, one per thread (zero-pad tail)
                int rr = tid >> 5, c4 = tid & 31;
                float4 v = make_float4(0.f, 0.f, 0.f, 0.f);
                if (rb + rr < cnt)
                    v = ((const float4*)(feats + s_idx[rb + rr] * KD))[c4];
                ((float4*)&s_rows[rr][0])[c4] = v;
            }
            __syncthreads();
#pragma unroll
            for (int rr = 0; rr < 16; rr++) {
                const float  fa = s_rows[rr][i];                      // conflict-free
                const float4 fb = *(const float4*)&s_rows[rr][cb];    // warp broadcast
                a0 = fmaf(fa, fb.x, a0);
                a1 = fmaf(fa, fb.y, a1);
                a2 = fmaf(fa, fb.z, a2);
                a3 = fmaf(fa, fb.w, a3);
            }
        }
        *(float4*)&g_gram[c][i][cb] = make_float4(a0, a1, a2, a3);
    }

    // ---------------- Device-wide barrier ----------------
    if (tid == 0) {
        __threadfence();                 // publish g_gram
        atomicAdd(&g_ctrA, 1u);
    }
    if (b >= NCHOL) return;              // 111 blocks done
    if (tid == 0)
        while (atomicAdd(&g_ctrA, 0u) < GRID_N) __nanosleep(100);
    __syncthreads();
    __threadfence();                     // acquire

    // ---------------- Phase B: register-resident logdet ----------------
    // Thread (i,h) holds row i, cols [32h, 32h+32) in registers.
    float r[32];
    {
        const float4* src = (const float4*)&g_gram[0][i][32 * h];
        const int stride4 = KD * KD / 4;             // float4 stride between classes
#pragma unroll
        for (int t4 = 0; t4 < 8; t4++) {
            float4 v;
            if (b < NC) {
                v = __ldcg((const float4*)&g_gram[b][i][32 * h] + t4);
            } else {
                v = make_float4(0.f, 0.f, 0.f, 0.f);
#pragma unroll
                for (int cc = 0; cc < NC; cc++) {
                    float4 u = __ldcg(src + cc * stride4 + t4);
                    v.x += u.x; v.y += u.y; v.z += u.z; v.w += u.w;
                }
            }
            r[4 * t4 + 0] = v.x; r[4 * t4 + 1] = v.y;
            r[4 * t4 + 2] = v.z; r[4 * t4 + 3] = v.w;
        }
        const int d = i - 32 * h;
        if (d >= 0 && d < 32) r[d] += 0.5f;          // + 0.5 I
    }

    for (int k = 0; k < KD; k++) {
        const int par = k & 1;
        if (i == k) {                    // 4 publisher threads write row k
            float4* dst = (float4*)&s_rowk[par][32 * h];
#pragma unroll
            for (int t4 = 0; t4 < 8; t4++)
                dst[t4] = make_float4(r[4 * t4 + 0], r[4 * t4 + 1],
                                      r[4 * t4 + 2], r[4 * t4 + 3]);
        }
        __syncthreads();
        if (tid == 0) s_piv[k] = s_rowk[par][k];
        if (i > k) {
            float piv = s_rowk[par][k];              // broadcast
            float inv;
            asm("rcp.approx.f32 %0, %1;" : "=f"(inv) : "f"(piv));
            const float naik = -s_rowk[par][i] * inv;    // -A[i][k]/A[k][k]
            const float4* col = (const float4*)&s_rowk[par][32 * h];
#pragma unroll
            for (int t4 = 0; t4 < 8; t4++) {
                float4 cv = col[t4];
                r[4 * t4 + 0] = fmaf(naik, cv.x, r[4 * t4 + 0]);
                r[4 * t4 + 1] = fmaf(naik, cv.y, r[4 * t4 + 1]);
                r[4 * t4 + 2] = fmaf(naik, cv.z, r[4 * t4 + 2]);
                r[4 * t4 + 3] = fmaf(naik, cv.w, r[4 * t4 + 3]);
            }
        }
    }
    __syncthreads();

    // logdet = sum log(pivots)
    if (h == 0) {
        float v = logf(s_piv[i]);
#pragma unroll
        for (int o = 16; o > 0; o >>= 1)
            v += __shfl_xor_sync(0xffffffffu, v, o);
        if ((i & 31) == 0) s_red[i >> 5] = v;
    }
    __syncthreads();
    if (tid == 0) {
        float ld = s_red[0] + s_red[1] + s_red[2] + s_red[3];
        atomicAdd(&g_acc, (b < NC) ? ld : -ld);
        __threadfence();
        unsigned old = atomicAdd(&g_ctrB, 1u);
        if (old == NCHOL - 1) {          // last of the 17
            float acc = atomicExch(&g_acc, 0.f);     // read + reset
            out[0] = acc + 1920.0f * 0.69314718055994530942f;
            atomicExch(&g_ctrA, 0u);                 // reset for next replay
            atomicExch(&g_ctrB, 0u);
        }
    }
}

extern "C" void kernel_launch(void* const* d_in, const int* in_sizes, int n_in,
                              void* d_out, int out_size) {
    const float* feats  = (const float*)d_in[0];
    const int*   labels = (const int*)d_in[1];
    // d_in[2] = ious: unused (reference uses coef = ones_like(ious))

    fused_kernel<<<GRID_N, 512>>>(feats, labels, (float*)d_out);
}

// round 13
// speedup vs baseline: 1.0711x; 1.0711x over previous
#include <cuda_runtime.h>
#include <math.h>

// loss = sum_c logdet(G_c + 0.5 I_128) - logdet(G + 0.5 I_128) + 1920*ln2
// where G_c = F_c^T F_c (per-class 128x128 Gram), G = sum_c G_c.
// Derivation: det(sI_m + F F^T) = s^(m-k) det(sI_k + F^T F).

#define MF 1536
#define KD 128
#define NC 16
#define NSLAB 8
#define SLABW 16                 // KD / NSLAB
#define NCHOL (NC + 1)

__device__ __align__(16) float g_gram[NC][KD][KD];

// ---------------------------------------------------------------------------
// Kernel 1: Gram slabs, NO accumulation. grid = NC*NSLAB = 128 blocks,
// 512 threads. Block (c, sl): thread (i = tid&127, h = tid>>7) computes
// G_c[i][16*sl + 4h .. +4] and stores it directly (STG.128).
// Block 0 thread 0 also initializes out[0] with the constant bias.
// ---------------------------------------------------------------------------
__global__ __launch_bounds__(512) void gram_kernel(const float* __restrict__ feats,
                                                   const int* __restrict__ labels,
                                                   float* __restrict__ out) {
    const int b   = blockIdx.x;
    const int c   = b >> 3;      // class
    const int sl  = b & 7;       // slab
    const int tid = threadIdx.x;
    const int i   = tid & 127;   // output row
    const int h   = tid >> 7;    // 0..3
    const int cb  = SLABW * sl + 4 * h;   // this thread's 4 output cols

    __shared__ int   s_idx[MF];
    __shared__ int   s_cnt;
    __shared__ __align__(16) float s_rows[16][KD];

    if (b == 0 && tid == 0)
        out[0] = 1920.0f * 0.69314718055994530942f;

    if (tid == 0) s_cnt = 0;
    __syncthreads();
    for (int m = tid; m < MF; m += 512)
        if (labels[m] == c) s_idx[atomicAdd(&s_cnt, 1)] = m;
    __syncthreads();
    const int cnt = s_cnt;

    float a0 = 0.f, a1 = 0.f, a2 = 0.f, a3 = 0.f;
    for (int rb = 0; rb < cnt; rb += 16) {
        __syncthreads();         // s_rows reuse guard
        {   // 16 rows x 128 floats = 512 float4, one per thread (zero-pad tail)
            int rr = tid >> 5, c4 = tid & 31;
            float4 v = make_float4(0.f, 0.f, 0.f, 0.f);
            if (rb + rr < cnt)
                v = ((const float4*)(feats + s_idx[rb + rr] * KD))[c4];
            ((float4*)&s_rows[rr][0])[c4] = v;
        }
        __syncthreads();
#pragma unroll
        for (int rr = 0; rr < 16; rr++) {
            const float  fa = s_rows[rr][i];                    // conflict-free
            const float4 fb = *(const float4*)&s_rows[rr][cb];  // broadcast
            a0 = fmaf(fa, fb.x, a0);
            a1 = fmaf(fa, fb.y, a1);
            a2 = fmaf(fa, fb.z, a2);
            a3 = fmaf(fa, fb.w, a3);
        }
    }
    *(float4*)&g_gram[c][i][cb] = make_float4(a0, a1, a2, a3);
}

// ---------------------------------------------------------------------------
// Kernel 2: logdet of 17 SPD 128x128 matrices, register-resident rows,
// PANEL-2 elimination (two pivots per barrier). Thread (i,h) holds row i
// cols [32h,32h+32) in registers. Per super-step k (k += 2): owners of rows
// k and k+1 publish their raw rows u, v (updated through step k-1) into a
// parity double buffer. Consumers (i > k+1) fold both elimination steps:
//   invk = 1/u[k];  c = -v[k]*invk;  pk1 = v[k+1] + c*u[k+1]
//   m1 = -u[i]*invk;  m2 = -(v[i] + c*u[i])/pk1;  e1 = m1 + m2*c
//   r[j] += e1*u[j] + m2*v[j]          (identical FLOP count to 2 steps)
// Dead column chunks (entirely < k) are skipped: h is warp-uniform so the
// chunk guard is a uniform branch. Pivots u[k], pk1 -> s_piv.
// Each block atomicAdds +/- sum(log(piv)) into out[0] (bias pre-written).
// ---------------------------------------------------------------------------
__global__ __launch_bounds__(512) void chol_kernel(float* __restrict__ out) {
    const int b   = blockIdx.x;
    const int tid = threadIdx.x;
    const int i   = tid & 127;   // owned matrix row
    const int h   = tid >> 7;    // segment: columns [32h, 32h+32)

    __shared__ __align__(16) float s_u[2][KD];
    __shared__ __align__(16) float s_v[2][KD];
    __shared__ float s_piv[KD];
    __shared__ float s_red[4];

    // Load row segment; block 16 sums the 16 class Grams (deep-MLP L2 hits).
    float r[32];
    {
#pragma unroll
        for (int t4 = 0; t4 < 8; t4++) {
            float4 v;
            if (b < NC) {
                v = ((const float4*)&g_gram[b][i][32 * h])[t4];
            } else {
                v = make_float4(0.f, 0.f, 0.f, 0.f);
#pragma unroll
                for (int cc = 0; cc < NC; cc++) {
                    float4 u = ((const float4*)&g_gram[cc][i][32 * h])[t4];
                    v.x += u.x; v.y += u.y; v.z += u.z; v.w += u.w;
                }
            }
            r[4 * t4 + 0] = v.x; r[4 * t4 + 1] = v.y;
            r[4 * t4 + 2] = v.z; r[4 * t4 + 3] = v.w;
        }
        const int d = i - 32 * h;
        if (d >= 0 && d < 32) r[d] += 0.5f;     // + 0.5 I
    }

    for (int k = 0; k < KD; k += 2) {
        const int par = (k >> 1) & 1;
        if (i == k) {                        // row k -> u  (4 warps, 8 STS.128 each)
            float4* dst = (float4*)&s_u[par][32 * h];
#pragma unroll
            for (int t4 = 0; t4 < 8; t4++)
                dst[t4] = make_float4(r[4 * t4 + 0], r[4 * t4 + 1],
                                      r[4 * t4 + 2], r[4 * t4 + 3]);
        } else if (i == k + 1) {             // row k+1 -> v
            float4* dst = (float4*)&s_v[par][32 * h];
#pragma unroll
            for (int t4 = 0; t4 < 8; t4++)
                dst[t4] = make_float4(r[4 * t4 + 0], r[4 * t4 + 1],
                                      r[4 * t4 + 2], r[4 * t4 + 3]);
        }
        __syncthreads();

        const float uk  = s_u[par][k];
        float invk;
        asm("rcp.approx.f32 %0, %1;" : "=f"(invk) : "f"(uk));
        const float c2  = -s_v[par][k] * invk;
        const float pk1 = fmaf(c2, s_u[par][k + 1], s_v[par][k + 1]);
        if (tid == 0) { s_piv[k] = uk; s_piv[k + 1] = pk1; }

        if (i > k + 1) {
            float invk1;
            asm("rcp.approx.f32 %0, %1;" : "=f"(invk1) : "f"(pk1));
            const float ui = s_u[par][i];            // = A[i][k]   (symmetry)
            const float vi = s_v[par][i];            // = A[i][k+1] (raw)
            const float m1 = -ui * invk;
            const float m2 = -fmaf(c2, ui, vi) * invk1;
            const float e1 = fmaf(m2, c2, m1);
            const float4* uu4 = (const float4*)&s_u[par][32 * h];
            const float4* vv4 = (const float4*)&s_v[par][32 * h];
#pragma unroll
            for (int t4 = 0; t4 < 8; t4++) {
                if (32 * h + 4 * t4 + 4 > k) {       // live chunk (warp-uniform)
                    float4 uu = uu4[t4];
                    float4 vv = vv4[t4];
                    r[4 * t4 + 0] = fmaf(e1, uu.x, fmaf(m2, vv.x, r[4 * t4 + 0]));
                    r[4 * t4 + 1] = fmaf(e1, uu.y, fmaf(m2, vv.y, r[4 * t4 + 1]));
                    r[4 * t4 + 2] = fmaf(e1, uu.z, fmaf(m2, vv.z, r[4 * t4 + 2]));
                    r[4 * t4 + 3] = fmaf(e1, uu.w, fmaf(m2, vv.w, r[4 * t4 + 3]));
                }
            }
        }
    }
    __syncthreads();

    // logdet = sum log(pivots); 128 parallel logs + warp/smem reduction.
    if (h == 0) {
        float v = logf(s_piv[i]);
#pragma unroll
        for (int o = 16; o > 0; o >>= 1)
            v += __shfl_xor_sync(0xffffffffu, v, o);
        if ((i & 31) == 0) s_red[i >> 5] = v;
    }
    __syncthreads();
    if (tid == 0) {
        float ld = s_red[0] + s_red[1] + s_red[2] + s_red[3];
        atomicAdd(out, (b < NC) ? ld : -ld);
    }
}

extern "C" void kernel_launch(void* const* d_in, const int* in_sizes, int n_in,
                              void* d_out, int out_size) {
    const float* feats  = (const float*)d_in[0];
    const int*   labels = (const int*)d_in[1];
    // d_in[2] = ious: unused (reference uses coef = ones_like(ious))
    float* out = (float*)d_out;

    gram_kernel<<<NC * NSLAB, 512>>>(feats, labels, out);
    chol_kernel<<<NCHOL, 512>>>(out);
}

// round 14
// speedup vs baseline: 1.3476x; 1.2581x over previous
#include <cuda_runtime.h>
#include <math.h>

// loss = sum_c logdet(G_c + 0.5 I_128) - logdet(G + 0.5 I_128) + 1920*ln2
// where G_c = F_c^T F_c (per-class 128x128 Gram), G = sum_c G_c.
// Derivation: det(sI_m + F F^T) = s^(m-k) det(sI_k + F^T F).

#define MF 1536
#define KD 128
#define NC 16
#define NSLAB 8
#define SLABW 16                 // KD / NSLAB
#define NCHOL (NC + 1)

typedef unsigned long long u64t;

__device__ __align__(16) float g_gram[NC][KD][KD];

__device__ __forceinline__ u64t pack2(float a, float b) {
    u64t r; asm("mov.b64 %0, {%1, %2};" : "=l"(r) : "f"(a), "f"(b)); return r;
}
// packed d = a*b + c on two f32 lanes (FFMA2; PTX-only form)
__device__ __forceinline__ u64t fma2(u64t a, u64t b, u64t c) {
    u64t d; asm("fma.rn.f32x2 %0, %1, %2, %3;" : "=l"(d) : "l"(a), "l"(b), "l"(c));
    return d;
}

// ---------------------------------------------------------------------------
// Kernel 1: Gram slabs, no accumulation. grid = NC*NSLAB = 128 blocks,
// 512 threads. Block (c, sl): thread (i = tid&127, h = tid>>7) computes
// G_c[i][16*sl + 4h .. +4] and stores it directly (STG.128).
// Block 0 thread 0 also initializes out[0] with the constant bias.
// ---------------------------------------------------------------------------
__global__ __launch_bounds__(512) void gram_kernel(const float* __restrict__ feats,
                                                   const int* __restrict__ labels,
                                                   float* __restrict__ out) {
    const int b   = blockIdx.x;
    const int c   = b >> 3;
    const int sl  = b & 7;
    const int tid = threadIdx.x;
    const int i   = tid & 127;
    const int h   = tid >> 7;
    const int cb  = SLABW * sl + 4 * h;

    __shared__ int   s_idx[MF];
    __shared__ int   s_cnt;
    __shared__ __align__(16) float s_rows[16][KD];

    if (b == 0 && tid == 0)
        out[0] = 1920.0f * 0.69314718055994530942f;

    if (tid == 0) s_cnt = 0;
    __syncthreads();
    for (int m = tid; m < MF; m += 512)
        if (labels[m] == c) s_idx[atomicAdd(&s_cnt, 1)] = m;
    __syncthreads();
    const int cnt = s_cnt;

    float a0 = 0.f, a1 = 0.f, a2 = 0.f, a3 = 0.f;
    for (int rb = 0; rb < cnt; rb += 16) {
        __syncthreads();
        {
            int rr = tid >> 5, c4 = tid & 31;
            float4 v = make_float4(0.f, 0.f, 0.f, 0.f);
            if (rb + rr < cnt)
                v = ((const float4*)(feats + s_idx[rb + rr] * KD))[c4];
            ((float4*)&s_rows[rr][0])[c4] = v;
        }
        __syncthreads();
#pragma unroll
        for (int rr = 0; rr < 16; rr++) {
            const float  fa = s_rows[rr][i];
            const float4 fb = *(const float4*)&s_rows[rr][cb];
            a0 = fmaf(fa, fb.x, a0);
            a1 = fmaf(fa, fb.y, a1);
            a2 = fmaf(fa, fb.z, a2);
            a3 = fmaf(fa, fb.w, a3);
        }
    }
    *(float4*)&g_gram[c][i][cb] = make_float4(a0, a1, a2, a3);
}

// ---------------------------------------------------------------------------
// Kernel 2: logdet of 17 SPD 128x128 matrices. Register-resident 4x8 tiles
// (thread (rg = tid>>4, cs = tid&15) owns rows 4rg..4rg+3, cols 8cs..8cs+8),
// stored as packed f32x2 pairs; trailing update uses fma.rn.f32x2.
// Panel-2 symmetric Gaussian elimination, one barrier per 2 pivots:
//   u = raw row k, v = raw row k+1 (both in the publisher tile: same rg)
//   invk = 1/u[k];  c2 = -v[k]*invk;  pk1 = v[k+1] + c2*u[k+1]
//   m1 = -u[i]*invk;  m2 = -(v[i]+c2*u[i])/pk1;  e1 = m1 + m2*c2
//   row_i += e1*u + m2*v      (multipliers SEL'd to 0 for dead rows)
// Dead rows/cols hold garbage; never read (pivots and multipliers only touch
// live entries; trailing block symmetry gives u[i] = A[i][k]).
// logdet = sum log(pivots); each block atomicAdds +/- it into out[0].
// ---------------------------------------------------------------------------
__global__ __launch_bounds__(512) void chol_kernel(float* __restrict__ out) {
    const int b   = blockIdx.x;
    const int tid = threadIdx.x;
    const int rg  = tid >> 4;     // row group: rows 4rg..4rg+3
    const int cs  = tid & 15;     // col segment: cols 8cs..8cs+8
    const int r0  = rg << 2;
    const int c0  = cs << 3;

    __shared__ __align__(16) float s_u[2][KD];
    __shared__ __align__(16) float s_v[2][KD];
    __shared__ float s_piv[KD];
    __shared__ float s_red[4];

    // Load 4x8 tile (block 16 sums all class Grams), +0.5 diag, pack to f32x2.
    u64t R[4][4];
#pragma unroll
    for (int d = 0; d < 4; d++) {
        const int row = r0 + d;
        float4 x, y;
        if (b < NC) {
            x = ((const float4*)&g_gram[b][row][c0])[0];
            y = ((const float4*)&g_gram[b][row][c0])[1];
        } else {
            x = make_float4(0.f, 0.f, 0.f, 0.f);
            y = make_float4(0.f, 0.f, 0.f, 0.f);
#pragma unroll
            for (int cc = 0; cc < NC; cc++) {
                float4 u = ((const float4*)&g_gram[cc][row][c0])[0];
                float4 w = ((const float4*)&g_gram[cc][row][c0])[1];
                x.x += u.x; x.y += u.y; x.z += u.z; x.w += u.w;
                y.x += w.x; y.y += w.y; y.z += w.z; y.w += w.w;
            }
        }
        const int dc = row - c0;          // diagonal position within segment
        if (dc >= 0 && dc < 8) {
            float* fx = (dc < 4) ? &x.x : &y.x;
            fx[dc & 3] += 0.5f;
        }
        R[d][0] = pack2(x.x, x.y); R[d][1] = pack2(x.z, x.w);
        R[d][2] = pack2(y.x, y.y); R[d][3] = pack2(y.z, y.w);
    }

    for (int k = 0; k < KD; k += 2) {
        const int par = (k >> 1) & 1;
        if (rg == (k >> 2)) {             // publisher: rows k,k+1 live here
            const int dk = k & 3;         // 0 or 2
            *(ulonglong2*)&s_u[par][c0]     = make_ulonglong2(R[dk][0], R[dk][1]);
            *(ulonglong2*)&s_u[par][c0 + 4] = make_ulonglong2(R[dk][2], R[dk][3]);
            *(ulonglong2*)&s_v[par][c0]     = make_ulonglong2(R[dk + 1][0], R[dk + 1][1]);
            *(ulonglong2*)&s_v[par][c0 + 4] = make_ulonglong2(R[dk + 1][2], R[dk + 1][3]);
        }
        __syncthreads();

        const float uk  = s_u[par][k];
        const float uk1 = s_u[par][k + 1];
        const float vk  = s_v[par][k];
        const float vk1 = s_v[par][k + 1];
        float invk;
        asm("rcp.approx.f32 %0, %1;" : "=f"(invk) : "f"(uk));
        const float c2  = -vk * invk;
        const float pk1 = fmaf(c2, uk1, vk1);
        if (tid == 0) { s_piv[k] = uk; s_piv[k + 1] = pk1; }

        if (r0 + 3 > k + 1) {             // tile has at least one live row
            float invk1;
            asm("rcp.approx.f32 %0, %1;" : "=f"(invk1) : "f"(pk1));
            // pivot-row segments (warp broadcast LDS.128s)
            const ulonglong2 ua = *(const ulonglong2*)&s_u[par][c0];
            const ulonglong2 ub = *(const ulonglong2*)&s_u[par][c0 + 4];
            const ulonglong2 va = *(const ulonglong2*)&s_v[par][c0];
            const ulonglong2 vb = *(const ulonglong2*)&s_v[par][c0 + 4];
            // per-row multiplier sources: u[r0..r0+3], v[r0..r0+3] (symmetry)
            const float4 um = *(const float4*)&s_u[par][r0];
            const float4 vm = *(const float4*)&s_v[par][r0];
            const float* ump = (const float*)&um;
            const float* vmp = (const float*)&vm;
#pragma unroll
            for (int d = 0; d < 4; d++) {
                const bool live = (r0 + d > k + 1);
                const float ui = ump[d], vi = vmp[d];
                float m1 = -ui * invk;
                float m2 = -fmaf(c2, ui, vi) * invk1;
                float e1 = fmaf(m2, c2, m1);
                m2 = live ? m2 : 0.f;      // SEL, no branch (NaN selected out)
                e1 = live ? e1 : 0.f;
                const u64t E = pack2(e1, e1);
                const u64t M = pack2(m2, m2);
                R[d][0] = fma2(E, ua.x, fma2(M, va.x, R[d][0]));
                R[d][1] = fma2(E, ua.y, fma2(M, va.y, R[d][1]));
                R[d][2] = fma2(E, ub.x, fma2(M, vb.x, R[d][2]));
                R[d][3] = fma2(E, ub.y, fma2(M, vb.y, R[d][3]));
            }
        }
    }
    __syncthreads();

    // logdet = sum log(pivots)
    if (tid < KD) {
        float v = logf(s_piv[tid]);
#pragma unroll
        for (int o = 16; o > 0; o >>= 1)
            v += __shfl_xor_sync(0xffffffffu, v, o);
        if ((tid & 31) == 0) s_red[tid >> 5] = v;
    }
    __syncthreads();
    if (tid == 0) {
        float ld = s_red[0] + s_red[1] + s_red[2] + s_red[3];
        atomicAdd(out, (b < NC) ? ld : -ld);
    }
}

extern "C" void kernel_launch(void* const* d_in, const int* in_sizes, int n_in,
                              void* d_out, int out_size) {
    const float* feats  = (const float*)d_in[0];
    const int*   labels = (const int*)d_in[1];
    // d_in[2] = ious: unused (reference uses coef = ones_like(ious))
    float* out = (float*)d_out;

    gram_kernel<<<NC * NSLAB, 512>>>(feats, labels, out);
    chol_kernel<<<NCHOL, 512>>>(out);
}